// round 9
// baseline (speedup 1.0000x reference)
#include <cuda_runtime.h>
#include <math.h>
#include <stdint.h>

// Problem constants
#define BATCH 2
#define NSEQ 2048
#define DIM 1024
#define HEADS 16
#define DHEAD 64
#define INNER (HEADS * DHEAD)      // 1024
#define QKV_W (3 * INNER)          // 3072
#define ROWS (BATCH * NSEQ)        // 4096
#define SCALE 0.125f               // 64^-0.5
#define LN_EPS 1e-5f
#define LOG2E 1.4426950408889634f

// Scratch (device globals: allocation-free rule)
__device__ float g_xn[ROWS * DIM];         // 16 MB (tf32-rounded)
__device__ float g_qkv[ROWS * QKV_W];      // 48 MB (tf32-rounded by GEMM1)
__device__ float g_attn[ROWS * INNER];     // 16 MB (tf32-rounded)
__device__ float g_wqkvT[QKV_W * DIM];     // 12 MB (tf32-rounded, transposed [N][K])
__device__ float g_woutT[DIM * INNER];     //  4 MB (tf32-rounded, transposed [N][K])

// ---------------------------------------------------------------------------
// helpers
// ---------------------------------------------------------------------------
__device__ __forceinline__ uint32_t cvt_tf32(float f) {
    uint32_t r;
    asm("cvt.rna.tf32.f32 %0, %1;" : "=r"(r) : "f"(f));
    return r;
}
__device__ __forceinline__ float rnd_tf32(float f) {
    return __uint_as_float(cvt_tf32(f));
}
__device__ __forceinline__ float exp2_fast(float x) {
    float y;
    asm("ex2.approx.ftz.f32 %0, %1;" : "=f"(y) : "f"(x));
    return y;
}
__device__ __forceinline__ float trunc_tf32(float f) {
    return __uint_as_float(__float_as_uint(f) & 0xFFFFE000u);
}

__device__ __forceinline__ void mma_tf32(float c[4],
                                         uint32_t a0, uint32_t a1, uint32_t a2, uint32_t a3,
                                         uint32_t b0, uint32_t b1) {
    asm volatile(
        "mma.sync.aligned.m16n8k8.row.col.f32.tf32.tf32.f32 "
        "{%0,%1,%2,%3}, {%4,%5,%6,%7}, {%8,%9}, {%0,%1,%2,%3};"
        : "+f"(c[0]), "+f"(c[1]), "+f"(c[2]), "+f"(c[3])
        : "r"(a0), "r"(a1), "r"(a2), "r"(a3), "r"(b0), "r"(b1));
}

__device__ __forceinline__ void ldsm_x4(uint32_t r[4], uint32_t addr) {
    asm volatile("ldmatrix.sync.aligned.m8n8.x4.shared.b16 {%0,%1,%2,%3}, [%4];"
                 : "=r"(r[0]), "=r"(r[1]), "=r"(r[2]), "=r"(r[3]) : "r"(addr));
}

__device__ __forceinline__ void cp_async16(uint32_t dst, const void* src) {
    asm volatile("cp.async.cg.shared.global [%0], [%1], 16;" :: "r"(dst), "l"(src));
}
__device__ __forceinline__ void cp_commit() {
    asm volatile("cp.async.commit_group;");
}
template <int N>
__device__ __forceinline__ void cp_wait() {
    asm volatile("cp.async.wait_group %0;" :: "n"(N));
}

// ---------------------------------------------------------------------------
// transpose + tf32-round: src [R][C] -> dst [C][R]. R,C multiples of 32.
// ---------------------------------------------------------------------------
__global__ __launch_bounds__(256) void transpose_round_kernel(
    const float* __restrict__ src, float* __restrict__ dst, int R, int C)
{
    __shared__ float t[32][33];
    const int bx = blockIdx.x * 32;
    const int by = blockIdx.y * 32;
    const int tx = threadIdx.x;
    const int ty = threadIdx.y;

    #pragma unroll
    for (int i = 0; i < 4; i++)
        t[ty + i * 8][tx] = src[(size_t)(by + ty + i * 8) * C + bx + tx];
    __syncthreads();
    #pragma unroll
    for (int i = 0; i < 4; i++)
        dst[(size_t)(bx + ty + i * 8) * R + by + tx] = rnd_tf32(t[tx][ty + i * 8]);
}

// ---------------------------------------------------------------------------
// LayerNorm, warp-per-row: 256 threads = 8 warps = 8 rows per block.
// No smem, no __syncthreads; shfl-only reductions. Emits tf32-rounded xn.
// ---------------------------------------------------------------------------
__global__ __launch_bounds__(256) void ln_kernel(
    const float* __restrict__ x,
    const float* __restrict__ gamma,
    const float* __restrict__ beta,
    float* __restrict__ xn)
{
    const int warp = threadIdx.x >> 5;
    const int lane = threadIdx.x & 31;
    const int row = blockIdx.x * 8 + warp;
    const float* xr = x + (size_t)row * DIM;

    float4 v[8];
    #pragma unroll
    for (int i = 0; i < 8; i++)
        v[i] = *(const float4*)(xr + (lane + 32 * i) * 4);

    float s = 0.0f;
    #pragma unroll
    for (int i = 0; i < 8; i++) s += v[i].x + v[i].y + v[i].z + v[i].w;
    #pragma unroll
    for (int o = 16; o > 0; o >>= 1) s += __shfl_xor_sync(0xffffffffu, s, o);
    const float mu = s * (1.0f / DIM);

    float sq = 0.0f;
    #pragma unroll
    for (int i = 0; i < 8; i++) {
        v[i].x -= mu; v[i].y -= mu; v[i].z -= mu; v[i].w -= mu;
        sq += v[i].x * v[i].x + v[i].y * v[i].y + v[i].z * v[i].z + v[i].w * v[i].w;
    }
    #pragma unroll
    for (int o = 16; o > 0; o >>= 1) sq += __shfl_xor_sync(0xffffffffu, sq, o);
    const float inv = rsqrtf(sq * (1.0f / DIM) + LN_EPS);

    float* orow = xn + (size_t)row * DIM;
    #pragma unroll
    for (int i = 0; i < 8; i++) {
        const int c = (lane + 32 * i) * 4;
        float4 g = *(const float4*)(gamma + c);
        float4 b = *(const float4*)(beta + c);
        float4 o;
        o.x = rnd_tf32(v[i].x * inv * g.x + b.x);
        o.y = rnd_tf32(v[i].y * inv * g.y + b.y);
        o.z = rnd_tf32(v[i].z * inv * g.z + b.z);
        o.w = rnd_tf32(v[i].w * inv * g.w + b.w);
        *(float4*)(orow + c) = o;
    }
}

// ---------------------------------------------------------------------------
// TF32 tensor-core GEMM, ldmatrix fragments, cp.async double buffer, BK=32.
// C[M,N] = A[M,K] @ B^T; A is [M][K], B given transposed as [N][K]; both
// already tf32-rounded. Block 256 thr (8 warps, 4m x 2n), 128x128 tile.
// roundC != 0 -> output is tf32-rounded (for tensors feeding later mmas).
// ---------------------------------------------------------------------------
#define LDT_ 36
#define STAGE_F (128 * LDT_)
__global__ __launch_bounds__(256) void tf32_gemm_ldsm(
    int M, int N, int K, int roundC,
    const float* __restrict__ A,
    const float* __restrict__ B,
    float* __restrict__ C)
{
    __shared__ float As[2][STAGE_F];
    __shared__ float Bs[2][STAGE_F];

    const int tid  = threadIdx.x;
    const int warp = tid >> 5;
    const int lane = tid & 31;
    const int lr = lane >> 2;
    const int lc = lane & 3;

    const int wm = (warp & 3) * 32;
    const int wn = (warp >> 2) * 64;

    A += (size_t)blockIdx.y * 128 * K;
    B += (size_t)blockIdx.x * 128 * K;
    C += (size_t)blockIdx.y * 128 * N + blockIdx.x * 128;

    const int r0 = tid >> 3;
    const int kc = (tid & 7) * 4;

    const uint32_t asBase = (uint32_t)__cvta_generic_to_shared(As);
    const uint32_t bsBase = (uint32_t)__cvta_generic_to_shared(Bs);

    const int nSlab = K / 32;

    auto load_slab = [&](int s, int buf) {
        const int gk = s * 32 + kc;
        const uint32_t ad = asBase + (uint32_t)(buf * STAGE_F * 4);
        const uint32_t bd = bsBase + (uint32_t)(buf * STAGE_F * 4);
        #pragma unroll
        for (int i = 0; i < 4; i++) {
            const int r = r0 + i * 32;
            cp_async16(ad + (uint32_t)((r * LDT_ + kc) * 4), A + (size_t)r * K + gk);
            cp_async16(bd + (uint32_t)((r * LDT_ + kc) * 4), B + (size_t)r * K + gk);
        }
    };

    const int aoff = (wm + (lane & 15)) * LDT_ + ((lane >> 4) << 2);
    const int boff = (wn + ((lane >> 4) << 3) + (lane & 7)) * LDT_ + (((lane >> 3) & 1) << 2);

    float acc[2][8][4] = {};

    load_slab(0, 0); cp_commit();

    for (int s = 0; s < nSlab; s++) {
        const int cur = s & 1;

        if (s + 1 < nSlab) load_slab(s + 1, cur ^ 1);
        cp_commit();

        cp_wait<1>();
        __syncthreads();

        const uint32_t aStage = asBase + (uint32_t)(cur * STAGE_F * 4);
        const uint32_t bStage = bsBase + (uint32_t)(cur * STAGE_F * 4);

        #pragma unroll
        for (int ks = 0; ks < 32; ks += 8) {
            uint32_t afr[2][4];
            #pragma unroll
            for (int mi = 0; mi < 2; mi++)
                ldsm_x4(afr[mi], aStage + (uint32_t)((aoff + mi * 16 * LDT_ + ks) * 4));
            uint32_t bfr[4][4];
            #pragma unroll
            for (int j = 0; j < 4; j++)
                ldsm_x4(bfr[j], bStage + (uint32_t)((boff + j * 16 * LDT_ + ks) * 4));
            #pragma unroll
            for (int mi = 0; mi < 2; mi++)
                #pragma unroll
                for (int j = 0; j < 4; j++) {
                    mma_tf32(acc[mi][2 * j],     afr[mi][0], afr[mi][1], afr[mi][2], afr[mi][3],
                             bfr[j][0], bfr[j][1]);
                    mma_tf32(acc[mi][2 * j + 1], afr[mi][0], afr[mi][1], afr[mi][2], afr[mi][3],
                             bfr[j][2], bfr[j][3]);
                }
        }
        __syncthreads();
    }

    if (roundC) {
        #pragma unroll
        for (int mi = 0; mi < 2; mi++)
            #pragma unroll
            for (int ni = 0; ni < 8; ni++)
                #pragma unroll
                for (int q = 0; q < 4; q++)
                    acc[mi][ni][q] = rnd_tf32(acc[mi][ni][q]);
    }

    #pragma unroll
    for (int mi = 0; mi < 2; mi++) {
        const int r = wm + 16 * mi + lr;
        #pragma unroll
        for (int ni = 0; ni < 8; ni++) {
            const int c0 = wn + 8 * ni + 2 * lc;
            *(float2*)(C + (size_t)r * N + c0)       = make_float2(acc[mi][ni][0], acc[mi][ni][1]);
            *(float2*)(C + (size_t)(r + 8) * N + c0) = make_float2(acc[mi][ni][2], acc[mi][ni][3]);
        }
    }
}

// ---------------------------------------------------------------------------
// FlashAttention, TF32 mma, exact (non-online) softmax, cp.async
// double-buffered K/V tiles (qkv is already tf32-rounded by GEMM1, so the
// loader is a pure 16B async copy — no cvt, no exposed load phase).
// Block = 256 threads (8 warps), 128 query rows per block for one (b,h).
// ---------------------------------------------------------------------------
__global__ __launch_bounds__(256) void attn_mma_kernel(
    const float* __restrict__ qkv,
    float* __restrict__ attn_out)
{
    const int bh = blockIdx.y;
    const int b = bh / HEADS;
    const int h = bh % HEADS;
    const int qbase = blockIdx.x * 128;
    const int warp = threadIdx.x >> 5;
    const int lane = threadIdx.x & 31;
    const int lr = lane >> 2;
    const int lc = lane & 3;

    __shared__ float Ks[2][64][72];
    __shared__ float Vs[2][64][68];

    const float* base = qkv + (size_t)b * NSEQ * QKV_W;
    const float NEG_INF = __int_as_float(0xff800000);
    const float QSCALE = SCALE * LOG2E;

    const int diagKt = qbase + ((warp & 4) << 4);

    const uint32_t ksBase = (uint32_t)__cvta_generic_to_shared(Ks);
    const uint32_t vsBase = (uint32_t)__cvta_generic_to_shared(Vs);

    // loader: K tile 64 rows x 16 chunks = 1024 chunks; same for V.
    // 256 threads x 4 iters each matrix.
    auto load_tile = [&](int kt, int buf) {
        const uint32_t kd = ksBase + (uint32_t)(buf * 64 * 72 * 4);
        const uint32_t vd = vsBase + (uint32_t)(buf * 64 * 68 * 4);
        #pragma unroll
        for (int it = 0; it < 4; it++) {
            const int idx = threadIdx.x + it * 256;
            const int r = idx >> 4;
            const int c = (idx & 15) << 2;
            const float* kr = base + (size_t)(kt + r) * QKV_W + INNER + h * DHEAD + c;
            cp_async16(kd + (uint32_t)((r * 72 + c) * 4), kr);
            cp_async16(vd + (uint32_t)((r * 68 + c) * 4), kr + INNER);
        }
    };

    // Q fragments (tf32, pre-scaled by SCALE*log2e, interleaved columns)
    uint32_t qa[8][4];
    {
        const int r0 = qbase + warp * 16 + lr;
        const float* q0 = base + (size_t)r0 * QKV_W + h * DHEAD;
        const float* q1 = q0 + (size_t)8 * QKV_W;
        #pragma unroll
        for (int s = 0; s < 8; s++) {
            const int d0 = 8 * s + 2 * lc;
            qa[s][0] = cvt_tf32(q0[d0] * QSCALE);
            qa[s][1] = cvt_tf32(q1[d0] * QSCALE);
            qa[s][2] = cvt_tf32(q0[d0 + 1] * QSCALE);
            qa[s][3] = cvt_tf32(q1[d0 + 1] * QSCALE);
        }
    }

    float oa[8][4] = {};
    float l0 = 0.0f, l1 = 0.0f;

    load_tile(0, 0); cp_commit();

    for (int ti = 0; ti < NSEQ / 64; ti++) {
        const int cur = ti & 1;
        const int kt = ti * 64;

        if (ti + 1 < NSEQ / 64) load_tile((ti + 1) * 64, cur ^ 1);
        cp_commit();

        cp_wait<1>();
        __syncthreads();

        // ---- S' = (Q*scale*log2e) @ K^T ----
        float sfr[8][4] = {};
        #pragma unroll
        for (int s = 0; s < 8; s++) {
            #pragma unroll
            for (int n = 0; n < 8; n++) {
                float2 kb = *(const float2*)(&Ks[cur][8 * n + lr][8 * s + 2 * lc]);
                mma_tf32(sfr[n], qa[s][0], qa[s][1], qa[s][2], qa[s][3],
                         __float_as_uint(kb.x), __float_as_uint(kb.y));
            }
        }

        // ---- diagonal mask (warp-local diagonal tile) ----
        if (kt == diagKt) {
            const int rloc0 = 16 * (warp & 3) + lr;
            const int rloc1 = rloc0 + 8;
            #pragma unroll
            for (int n = 0; n < 8; n++) {
                const int col0 = 8 * n + 2 * lc;
                if (col0 == rloc0)     sfr[n][0] = NEG_INF;
                if (col0 + 1 == rloc0) sfr[n][1] = NEG_INF;
                if (col0 == rloc1)     sfr[n][2] = NEG_INF;
                if (col0 + 1 == rloc1) sfr[n][3] = NEG_INF;
            }
        }

        // ---- P = trunc_tf32(exp2(S')) in place; l from same values ----
        #pragma unroll
        for (int n = 0; n < 8; n++) {
            sfr[n][0] = trunc_tf32(exp2_fast(sfr[n][0]));
            sfr[n][1] = trunc_tf32(exp2_fast(sfr[n][1]));
            sfr[n][2] = trunc_tf32(exp2_fast(sfr[n][2]));
            sfr[n][3] = trunc_tf32(exp2_fast(sfr[n][3]));
            l0 += sfr[n][0] + sfr[n][1];
            l1 += sfr[n][2] + sfr[n][3];
        }

        // ---- O += P @ V ----
        #pragma unroll
        for (int s = 0; s < 8; s++) {
            const uint32_t a0 = __float_as_uint(sfr[s][0]);
            const uint32_t a1 = __float_as_uint(sfr[s][2]);
            const uint32_t a2 = __float_as_uint(sfr[s][1]);
            const uint32_t a3 = __float_as_uint(sfr[s][3]);
            #pragma unroll
            for (int n = 0; n < 8; n++) {
                const uint32_t vb0 = __float_as_uint(Vs[cur][8 * s + 2 * lc][8 * n + lr]);
                const uint32_t vb1 = __float_as_uint(Vs[cur][8 * s + 2 * lc + 1][8 * n + lr]);
                mma_tf32(oa[n], a0, a1, a2, a3, vb0, vb1);
            }
        }

        __syncthreads();   // all warps done with buffer cur before next load
    }

    l0 += __shfl_xor_sync(0xffffffffu, l0, 1);
    l0 += __shfl_xor_sync(0xffffffffu, l0, 2);
    l1 += __shfl_xor_sync(0xffffffffu, l1, 1);
    l1 += __shfl_xor_sync(0xffffffffu, l1, 2);
    const float inv0 = 1.0f / l0;
    const float inv1 = 1.0f / l1;

    const int row0 = qbase + 16 * warp + lr;
    float* o0 = attn_out + ((size_t)b * NSEQ + row0) * INNER + h * DHEAD;
    float* o1 = o0 + (size_t)8 * INNER;
    #pragma unroll
    for (int n = 0; n < 8; n++) {
        const int c = 8 * n + 2 * lc;
        *(float2*)(o0 + c) = make_float2(rnd_tf32(oa[n][0] * inv0), rnd_tf32(oa[n][1] * inv0));
        *(float2*)(o1 + c) = make_float2(rnd_tf32(oa[n][2] * inv1), rnd_tf32(oa[n][3] * inv1));
    }
}

// ---------------------------------------------------------------------------
extern "C" void kernel_launch(void* const* d_in, const int* in_sizes, int n_in,
                              void* d_out, int out_size)
{
    const float* x      = (const float*)d_in[0];
    const float* gamma  = (const float*)d_in[1];
    const float* beta   = (const float*)d_in[2];
    const float* w_qkv  = (const float*)d_in[3];
    const float* w_out  = (const float*)d_in[4];
    float* out = (float*)d_out;

    float *xn, *qkv, *attn, *wqkvT, *woutT;
    cudaGetSymbolAddress((void**)&xn,    g_xn);
    cudaGetSymbolAddress((void**)&qkv,   g_qkv);
    cudaGetSymbolAddress((void**)&attn,  g_attn);
    cudaGetSymbolAddress((void**)&wqkvT, g_wqkvT);
    cudaGetSymbolAddress((void**)&woutT, g_woutT);

    // 0) transpose + round weights: [K][N] -> [N][K] tf32
    {
        dim3 blk(32, 8);
        dim3 g1(QKV_W / 32, DIM / 32);
        transpose_round_kernel<<<g1, blk>>>(w_qkv, wqkvT, DIM, QKV_W);
        dim3 g2(DIM / 32, INNER / 32);
        transpose_round_kernel<<<g2, blk>>>(w_out, woutT, INNER, DIM);
    }

    // 1) LayerNorm (warp-per-row; emits tf32-rounded)
    ln_kernel<<<ROWS / 8, 256>>>(x, gamma, beta, xn);

    // 2) QKV projection: [4096,1024] @ [1024,3072], tf32-rounded output
    {
        dim3 grid(QKV_W / 128, ROWS / 128);
        tf32_gemm_ldsm<<<grid, 256>>>(ROWS, QKV_W, DIM, 1, xn, wqkvT, qkv);
    }

    // 3) attention (128 q-rows per block, double-buffered K/V)
    {
        dim3 grid(NSEQ / 128, BATCH * HEADS);
        attn_mma_kernel<<<grid, 256>>>(qkv, attn);
    }

    // 4) output projection: [4096,1024] @ [1024,1024], full-precision output
    {
        dim3 grid(DIM / 128, ROWS / 128);
        tf32_gemm_ldsm<<<grid, 256>>>(ROWS, DIM, INNER, 0, attn, woutT, out);
    }
}

// round 11
// speedup vs baseline: 1.8403x; 1.8403x over previous
#include <cuda_runtime.h>
#include <cuda_fp16.h>
#include <math.h>
#include <stdint.h>

// Problem constants
#define BATCH 2
#define NSEQ 2048
#define DIM 1024
#define HEADS 16
#define DHEAD 64
#define INNER (HEADS * DHEAD)      // 1024
#define QKV_W (3 * INNER)          // 3072
#define ROWS (BATCH * NSEQ)        // 4096
#define SCALE 0.125f               // 64^-0.5
#define LN_EPS 1e-5f
#define LOG2E 1.4426950408889634f

// Scratch (device globals: allocation-free rule) — all fp16 now
__device__ __half g_xn[ROWS * DIM];        //  8 MB
__device__ __half g_qkv[ROWS * QKV_W];     // 24 MB
__device__ __half g_attn[ROWS * INNER];    //  8 MB
__device__ __half g_wqkvT[QKV_W * DIM];    //  6 MB (transposed [N][K])
__device__ __half g_woutT[DIM * INNER];    //  2 MB (transposed [N][K])

// ---------------------------------------------------------------------------
// helpers
// ---------------------------------------------------------------------------
__device__ __forceinline__ float exp2_fast(float x) {
    float y;
    asm("ex2.approx.ftz.f32 %0, %1;" : "=f"(y) : "f"(x));
    return y;
}
// pack two floats -> f16x2 (lo, hi), round-to-nearest
__device__ __forceinline__ uint32_t pack_h2(float lo, float hi) {
    uint32_t d;
    asm("cvt.rn.f16x2.f32 %0, %1, %2;" : "=r"(d) : "f"(hi), "f"(lo));
    return d;
}
__device__ __forceinline__ float2 unpack_h2(uint32_t u) {
    __half2 h = *reinterpret_cast<__half2*>(&u);
    return __half22float2(h);
}

__device__ __forceinline__ void mma_f16(float c[4],
                                        uint32_t a0, uint32_t a1, uint32_t a2, uint32_t a3,
                                        uint32_t b0, uint32_t b1) {
    asm volatile(
        "mma.sync.aligned.m16n8k16.row.col.f32.f16.f16.f32 "
        "{%0,%1,%2,%3}, {%4,%5,%6,%7}, {%8,%9}, {%0,%1,%2,%3};"
        : "+f"(c[0]), "+f"(c[1]), "+f"(c[2]), "+f"(c[3])
        : "r"(a0), "r"(a1), "r"(a2), "r"(a3), "r"(b0), "r"(b1));
}

__device__ __forceinline__ void ldsm_x4(uint32_t r[4], uint32_t addr) {
    asm volatile("ldmatrix.sync.aligned.m8n8.x4.shared.b16 {%0,%1,%2,%3}, [%4];"
                 : "=r"(r[0]), "=r"(r[1]), "=r"(r[2]), "=r"(r[3]) : "r"(addr));
}
__device__ __forceinline__ void ldsm_x4_t(uint32_t r[4], uint32_t addr) {
    asm volatile("ldmatrix.sync.aligned.m8n8.x4.trans.shared.b16 {%0,%1,%2,%3}, [%4];"
                 : "=r"(r[0]), "=r"(r[1]), "=r"(r[2]), "=r"(r[3]) : "r"(addr));
}

__device__ __forceinline__ void cp_async16(uint32_t dst, const void* src) {
    asm volatile("cp.async.cg.shared.global [%0], [%1], 16;" :: "r"(dst), "l"(src));
}
__device__ __forceinline__ void cp_commit() {
    asm volatile("cp.async.commit_group;");
}
template <int N>
__device__ __forceinline__ void cp_wait() {
    asm volatile("cp.async.wait_group %0;" :: "n"(N));
}

// ---------------------------------------------------------------------------
// transpose + fp16-convert: src f32 [R][C] -> dst f16 [C][R]. R,C mult of 32.
// ---------------------------------------------------------------------------
__global__ __launch_bounds__(256) void transpose_h_kernel(
    const float* __restrict__ src, __half* __restrict__ dst, int R, int C)
{
    __shared__ float t[32][33];
    const int bx = blockIdx.x * 32;
    const int by = blockIdx.y * 32;
    const int tx = threadIdx.x;
    const int ty = threadIdx.y;

    #pragma unroll
    for (int i = 0; i < 4; i++)
        t[ty + i * 8][tx] = src[(size_t)(by + ty + i * 8) * C + bx + tx];
    __syncthreads();
    #pragma unroll
    for (int i = 0; i < 4; i++)
        dst[(size_t)(bx + ty + i * 8) * R + by + tx] = __float2half_rn(t[tx][ty + i * 8]);
}

// ---------------------------------------------------------------------------
// LayerNorm: one block per row, 256 threads; emits fp16 xn
// ---------------------------------------------------------------------------
__global__ __launch_bounds__(256) void ln_kernel(
    const float* __restrict__ x,
    const float* __restrict__ gamma,
    const float* __restrict__ beta,
    __half* __restrict__ xn)
{
    __shared__ float red[8];
    const int row = blockIdx.x;
    const int tid = threadIdx.x;
    const float* xr = x + (size_t)row * DIM;

    float4 v = *(const float4*)(xr + tid * 4);

    float s = v.x + v.y + v.z + v.w;
    #pragma unroll
    for (int o = 16; o > 0; o >>= 1) s += __shfl_xor_sync(0xffffffffu, s, o);
    if ((tid & 31) == 0) red[tid >> 5] = s;
    __syncthreads();
    if (tid < 8) {
        float t = red[tid];
        #pragma unroll
        for (int o = 4; o > 0; o >>= 1) t += __shfl_xor_sync(0xffu, t, o);
        if (tid == 0) red[0] = t;
    }
    __syncthreads();
    const float mu = red[0] * (1.0f / DIM);
    __syncthreads();

    float d0 = v.x - mu, d1 = v.y - mu, d2 = v.z - mu, d3 = v.w - mu;
    float sq = d0 * d0 + d1 * d1 + d2 * d2 + d3 * d3;
    #pragma unroll
    for (int o = 16; o > 0; o >>= 1) sq += __shfl_xor_sync(0xffffffffu, sq, o);
    if ((tid & 31) == 0) red[tid >> 5] = sq;
    __syncthreads();
    if (tid < 8) {
        float t = red[tid];
        #pragma unroll
        for (int o = 4; o > 0; o >>= 1) t += __shfl_xor_sync(0xffu, t, o);
        if (tid == 0) red[0] = t;
    }
    __syncthreads();
    const float inv = rsqrtf(red[0] * (1.0f / DIM) + LN_EPS);

    const int c = tid * 4;
    float4 g = *(const float4*)(gamma + c);
    float4 b = *(const float4*)(beta + c);
    uint2 o;
    o.x = pack_h2(d0 * inv * g.x + b.x, d1 * inv * g.y + b.y);
    o.y = pack_h2(d2 * inv * g.z + b.z, d3 * inv * g.w + b.w);
    *(uint2*)(xn + (size_t)row * DIM + c) = o;
}

// ---------------------------------------------------------------------------
// FP16 tensor-core GEMM (m16n8k16), ldmatrix fragments, cp.async double
// buffer, BK=64 halves (128 B of K per slab). C[M,N] = A[M,K] @ B^T;
// A f16 [M][K], B f16 transposed [N][K]. Block 256 thr (8 warps, 4m x 2n),
// 128x128 tile. outHalf!=0 -> fp16 output, else fp32.
// Smem stride 72 halves (144 B): ldmatrix rows land on banks 4r..4r+3,
// covering all 32 banks (conflict-free).
// ---------------------------------------------------------------------------
#define LDT2 72
#define STAGE_H (128 * LDT2)     // halves per tile per stage (18432 B)
__global__ __launch_bounds__(256) void f16_gemm(
    int M, int N, int K, int outHalf,
    const __half* __restrict__ A,
    const __half* __restrict__ B,
    void* __restrict__ Cv)
{
    __shared__ __half As[2][STAGE_H];
    __shared__ __half Bs[2][STAGE_H];

    const int tid  = threadIdx.x;
    const int warp = tid >> 5;
    const int lane = tid & 31;
    const int lr = lane >> 2;
    const int lc = lane & 3;

    const int wm = (warp & 3) * 32;
    const int wn = (warp >> 2) * 64;

    A += (size_t)blockIdx.y * 128 * K;
    B += (size_t)blockIdx.x * 128 * K;
    const size_t cOff = (size_t)blockIdx.y * 128 * N + blockIdx.x * 128;

    // loader: 1024 16B-chunks (8 halves) per matrix per slab; 4 per thread
    const int r0 = tid >> 3;             // 0..31
    const int kc = (tid & 7) * 8;        // half-col 0..56

    const uint32_t asBase = (uint32_t)__cvta_generic_to_shared(As);
    const uint32_t bsBase = (uint32_t)__cvta_generic_to_shared(Bs);

    const int nSlab = K / 64;

    auto load_slab = [&](int s, int buf) {
        const int gk = s * 64 + kc;
        const uint32_t ad = asBase + (uint32_t)(buf * STAGE_H * 2);
        const uint32_t bd = bsBase + (uint32_t)(buf * STAGE_H * 2);
        #pragma unroll
        for (int i = 0; i < 4; i++) {
            const int r = r0 + i * 32;
            cp_async16(ad + (uint32_t)((r * LDT2 + kc) * 2), A + (size_t)r * K + gk);
            cp_async16(bd + (uint32_t)((r * LDT2 + kc) * 2), B + (size_t)r * K + gk);
        }
    };

    // ldmatrix offsets (halves within a stage)
    const int aoff = (wm + (lane & 15)) * LDT2 + ((lane >> 4) << 3);
    const int boff = (wn + ((lane >> 4) << 3) + (lane & 7)) * LDT2 + (((lane >> 3) & 1) << 3);

    float acc[2][8][4] = {};

    load_slab(0, 0); cp_commit();

    for (int s = 0; s < nSlab; s++) {
        const int cur = s & 1;

        if (s + 1 < nSlab) load_slab(s + 1, cur ^ 1);
        cp_commit();

        cp_wait<1>();
        __syncthreads();

        const uint32_t aStage = asBase + (uint32_t)(cur * STAGE_H * 2);
        const uint32_t bStage = bsBase + (uint32_t)(cur * STAGE_H * 2);

        #pragma unroll
        for (int ks = 0; ks < 64; ks += 16) {
            uint32_t afr[2][4];
            #pragma unroll
            for (int mi = 0; mi < 2; mi++)
                ldsm_x4(afr[mi], aStage + (uint32_t)((aoff + mi * 16 * LDT2 + ks) * 2));
            uint32_t bfr[4][4];
            #pragma unroll
            for (int j = 0; j < 4; j++)
                ldsm_x4(bfr[j], bStage + (uint32_t)((boff + j * 16 * LDT2 + ks) * 2));
            #pragma unroll
            for (int mi = 0; mi < 2; mi++)
                #pragma unroll
                for (int j = 0; j < 4; j++) {
                    mma_f16(acc[mi][2 * j],     afr[mi][0], afr[mi][1], afr[mi][2], afr[mi][3],
                            bfr[j][0], bfr[j][1]);
                    mma_f16(acc[mi][2 * j + 1], afr[mi][0], afr[mi][1], afr[mi][2], afr[mi][3],
                            bfr[j][2], bfr[j][3]);
                }
        }
        __syncthreads();
    }

    if (outHalf) {
        __half* C = (__half*)Cv + cOff;
        #pragma unroll
        for (int mi = 0; mi < 2; mi++) {
            const int r = wm + 16 * mi + lr;
            #pragma unroll
            for (int ni = 0; ni < 8; ni++) {
                const int c0 = wn + 8 * ni + 2 * lc;
                *(uint32_t*)(C + (size_t)r * N + c0)       = pack_h2(acc[mi][ni][0], acc[mi][ni][1]);
                *(uint32_t*)(C + (size_t)(r + 8) * N + c0) = pack_h2(acc[mi][ni][2], acc[mi][ni][3]);
            }
        }
    } else {
        float* C = (float*)Cv + cOff;
        #pragma unroll
        for (int mi = 0; mi < 2; mi++) {
            const int r = wm + 16 * mi + lr;
            #pragma unroll
            for (int ni = 0; ni < 8; ni++) {
                const int c0 = wn + 8 * ni + 2 * lc;
                *(float2*)(C + (size_t)r * N + c0)       = make_float2(acc[mi][ni][0], acc[mi][ni][1]);
                *(float2*)(C + (size_t)(r + 8) * N + c0) = make_float2(acc[mi][ni][2], acc[mi][ni][3]);
            }
        }
    }
}

// ---------------------------------------------------------------------------
// FlashAttention, FP16 mma (m16n8k16), exact (non-online) softmax.
// Block = 256 threads (8 warps), 128 query rows per block for one (b,h).
// K fragments via ldmatrix (non-trans), V via ldmatrix.x4.trans.
// P packed to fp16 in registers; l sums the same rounded values.
// ---------------------------------------------------------------------------
__global__ __launch_bounds__(256) void attn_mma_kernel(
    const __half* __restrict__ qkv,
    __half* __restrict__ attn_out)
{
    const int bh = blockIdx.y;
    const int b = bh / HEADS;
    const int h = bh % HEADS;
    const int qbase = blockIdx.x * 128;
    const int warp = threadIdx.x >> 5;
    const int lane = threadIdx.x & 31;
    const int lr = lane >> 2;
    const int lc = lane & 3;

    __shared__ __half Ks[64][LDT2];
    __shared__ __half Vs[64][LDT2];

    const __half* base = qkv + (size_t)b * NSEQ * QKV_W;
    const float NEG_INF = __int_as_float(0xff800000);
    const float QSCALE = SCALE * LOG2E;

    const int diagKt = qbase + ((warp & 4) << 4);

    const uint32_t ksBase = (uint32_t)__cvta_generic_to_shared(Ks);
    const uint32_t vsBase = (uint32_t)__cvta_generic_to_shared(Vs);

    // K fragment offset (non-trans): rows = keys, col = d
    const int koff = (((lane >> 4) << 3) + (lane & 7)) * LDT2 + (((lane >> 3) & 1) << 3);
    // V fragment offset (trans): rows = keys, col = d
    const int voff = ((((lane >> 3) & 1) << 3) + (lane & 7)) * LDT2 + ((lane >> 4) << 3);

    // ---- Q fragments (fp16 pairs, pre-scaled by SCALE*log2e) ----
    uint32_t qa[4][4];
    {
        const int r0 = qbase + warp * 16 + lr;
        const __half* q0 = base + (size_t)r0 * QKV_W + h * DHEAD;
        const __half* q1 = q0 + (size_t)8 * QKV_W;
        #pragma unroll
        for (int s = 0; s < 4; s++) {
            const int d0 = 16 * s + 2 * lc;
            qa[s][0] = pack_h2(__half2float(q0[d0])     * QSCALE, __half2float(q0[d0 + 1]) * QSCALE);
            qa[s][1] = pack_h2(__half2float(q1[d0])     * QSCALE, __half2float(q1[d0 + 1]) * QSCALE);
            qa[s][2] = pack_h2(__half2float(q0[d0 + 8]) * QSCALE, __half2float(q0[d0 + 9]) * QSCALE);
            qa[s][3] = pack_h2(__half2float(q1[d0 + 8]) * QSCALE, __half2float(q1[d0 + 9]) * QSCALE);
        }
    }

    float oa[8][4] = {};
    float l0 = 0.0f, l1 = 0.0f;

    for (int kt = 0; kt < NSEQ; kt += 64) {
        __syncthreads();

        // cooperative K/V tile load: 1024 uint4 (8 halves each), 4 per thread
        #pragma unroll
        for (int it = 0; it < 4; it++) {
            const int idx = threadIdx.x + it * 256;
            const int mat = idx >> 9;            // 0 = K, 1 = V
            const int r  = (idx >> 3) & 63;
            const int cc = (idx & 7) * 8;
            const __half* src = base + (size_t)(kt + r) * QKV_W + (1 + mat) * INNER + h * DHEAD + cc;
            __half* dst = (mat ? &Vs[r][cc] : &Ks[r][cc]);
            *(uint4*)dst = *(const uint4*)src;
        }
        __syncthreads();

        // ---- S' = (Q*scale*log2e) @ K^T : 4 ksteps (d) x 8 key-blocks ----
        float sfr[8][4] = {};
        #pragma unroll
        for (int s = 0; s < 4; s++) {
            #pragma unroll
            for (int j = 0; j < 4; j++) {
                uint32_t kb[4];
                ldsm_x4(kb, ksBase + (uint32_t)((16 * j * LDT2 + koff + 16 * s) * 2));
                mma_f16(sfr[2 * j],     qa[s][0], qa[s][1], qa[s][2], qa[s][3], kb[0], kb[1]);
                mma_f16(sfr[2 * j + 1], qa[s][0], qa[s][1], qa[s][2], qa[s][3], kb[2], kb[3]);
            }
        }

        // ---- diagonal mask (warp-local diagonal tile) ----
        if (kt == diagKt) {
            const int rloc0 = 16 * (warp & 3) + lr;
            const int rloc1 = rloc0 + 8;
            #pragma unroll
            for (int n = 0; n < 8; n++) {
                const int col0 = 8 * n + 2 * lc;
                if (col0 == rloc0)     sfr[n][0] = NEG_INF;
                if (col0 + 1 == rloc0) sfr[n][1] = NEG_INF;
                if (col0 == rloc1)     sfr[n][2] = NEG_INF;
                if (col0 + 1 == rloc1) sfr[n][3] = NEG_INF;
            }
        }

        // ---- P = f16(exp2(S')); pack A-fragments; l from rounded values ----
        uint32_t pa[4][4];
        #pragma unroll
        for (int s = 0; s < 4; s++) {
            pa[s][0] = pack_h2(exp2_fast(sfr[2 * s][0]),     exp2_fast(sfr[2 * s][1]));
            pa[s][1] = pack_h2(exp2_fast(sfr[2 * s][2]),     exp2_fast(sfr[2 * s][3]));
            pa[s][2] = pack_h2(exp2_fast(sfr[2 * s + 1][0]), exp2_fast(sfr[2 * s + 1][1]));
            pa[s][3] = pack_h2(exp2_fast(sfr[2 * s + 1][2]), exp2_fast(sfr[2 * s + 1][3]));
            float2 f0 = unpack_h2(pa[s][0]);
            float2 f1 = unpack_h2(pa[s][1]);
            float2 f2 = unpack_h2(pa[s][2]);
            float2 f3 = unpack_h2(pa[s][3]);
            l0 += f0.x + f0.y + f2.x + f2.y;
            l1 += f1.x + f1.y + f3.x + f3.y;
        }

        // ---- O += P @ V : 4 ksteps (keys) x 8 d-blocks; V via trans ----
        #pragma unroll
        for (int s = 0; s < 4; s++) {
            #pragma unroll
            for (int j = 0; j < 4; j++) {
                uint32_t vb[4];
                ldsm_x4_t(vb, vsBase + (uint32_t)((16 * s * LDT2 + voff + 16 * j) * 2));
                mma_f16(oa[2 * j],     pa[s][0], pa[s][1], pa[s][2], pa[s][3], vb[0], vb[1]);
                mma_f16(oa[2 * j + 1], pa[s][0], pa[s][1], pa[s][2], pa[s][3], vb[2], vb[3]);
            }
        }
    }

    l0 += __shfl_xor_sync(0xffffffffu, l0, 1);
    l0 += __shfl_xor_sync(0xffffffffu, l0, 2);
    l1 += __shfl_xor_sync(0xffffffffu, l1, 1);
    l1 += __shfl_xor_sync(0xffffffffu, l1, 2);
    const float inv0 = 1.0f / l0;
    const float inv1 = 1.0f / l1;

    const int row0 = qbase + 16 * warp + lr;
    __half* o0 = attn_out + ((size_t)b * NSEQ + row0) * INNER + h * DHEAD;
    __half* o1 = o0 + (size_t)8 * INNER;
    #pragma unroll
    for (int n = 0; n < 8; n++) {
        const int c = 8 * n + 2 * lc;
        *(uint32_t*)(o0 + c) = pack_h2(oa[n][0] * inv0, oa[n][1] * inv0);
        *(uint32_t*)(o1 + c) = pack_h2(oa[n][2] * inv1, oa[n][3] * inv1);
    }
}

// ---------------------------------------------------------------------------
extern "C" void kernel_launch(void* const* d_in, const int* in_sizes, int n_in,
                              void* d_out, int out_size)
{
    const float* x      = (const float*)d_in[0];
    const float* gamma  = (const float*)d_in[1];
    const float* beta   = (const float*)d_in[2];
    const float* w_qkv  = (const float*)d_in[3];
    const float* w_out  = (const float*)d_in[4];
    float* out = (float*)d_out;

    __half *xn, *qkv, *attn, *wqkvT, *woutT;
    cudaGetSymbolAddress((void**)&xn,    g_xn);
    cudaGetSymbolAddress((void**)&qkv,   g_qkv);
    cudaGetSymbolAddress((void**)&attn,  g_attn);
    cudaGetSymbolAddress((void**)&wqkvT, g_wqkvT);
    cudaGetSymbolAddress((void**)&woutT, g_woutT);

    // 0) transpose + convert weights: f32 [K][N] -> f16 [N][K]
    {
        dim3 blk(32, 8);
        dim3 g1(QKV_W / 32, DIM / 32);
        transpose_h_kernel<<<g1, blk>>>(w_qkv, wqkvT, DIM, QKV_W);
        dim3 g2(DIM / 32, INNER / 32);
        transpose_h_kernel<<<g2, blk>>>(w_out, woutT, INNER, DIM);
    }

    // 1) LayerNorm (emits fp16)
    ln_kernel<<<ROWS, 256>>>(x, gamma, beta, xn);

    // 2) QKV projection: [4096,1024] @ [1024,3072], fp16 output
    {
        dim3 grid(QKV_W / 128, ROWS / 128);
        f16_gemm<<<grid, 256>>>(ROWS, QKV_W, DIM, 1, xn, wqkvT, qkv);
    }

    // 3) attention (128 q-rows per block, fp16 mma)
    {
        dim3 grid(NSEQ / 128, BATCH * HEADS);
        attn_mma_kernel<<<grid, 256>>>(qkv, attn);
    }

    // 4) output projection: [4096,1024] @ [1024,1024], fp32 output
    {
        dim3 grid(DIM / 128, ROWS / 128);
        f16_gemm<<<grid, 256>>>(ROWS, DIM, INNER, 0, attn, woutT, out);
    }
}

// round 12
// speedup vs baseline: 1.9912x; 1.0820x over previous
#include <cuda_runtime.h>
#include <cuda_fp16.h>
#include <math.h>
#include <stdint.h>

// Problem constants
#define BATCH 2
#define NSEQ 2048
#define DIM 1024
#define HEADS 16
#define DHEAD 64
#define INNER (HEADS * DHEAD)      // 1024
#define QKV_W (3 * INNER)          // 3072
#define ROWS (BATCH * NSEQ)        // 4096
#define SCALE 0.125f               // 64^-0.5
#define LN_EPS 1e-5f
#define LOG2E 1.4426950408889634f

// Scratch (device globals: allocation-free rule) — all fp16
__device__ __half g_xn[ROWS * DIM];        //  8 MB
__device__ __half g_qkv[ROWS * QKV_W];     // 24 MB
__device__ __half g_attn[ROWS * INNER];    //  8 MB
__device__ __half g_wqkvT[QKV_W * DIM];    //  6 MB (transposed [N][K])
__device__ __half g_woutT[DIM * INNER];    //  2 MB (transposed [N][K])

// ---------------------------------------------------------------------------
// helpers
// ---------------------------------------------------------------------------
__device__ __forceinline__ float exp2_fast(float x) {
    float y;
    asm("ex2.approx.ftz.f32 %0, %1;" : "=f"(y) : "f"(x));
    return y;
}
__device__ __forceinline__ uint32_t pack_h2(float lo, float hi) {
    uint32_t d;
    asm("cvt.rn.f16x2.f32 %0, %1, %2;" : "=r"(d) : "f"(hi), "f"(lo));
    return d;
}
__device__ __forceinline__ float2 unpack_h2(uint32_t u) {
    __half2 h = *reinterpret_cast<__half2*>(&u);
    return __half22float2(h);
}

__device__ __forceinline__ void mma_f16(float c[4],
                                        uint32_t a0, uint32_t a1, uint32_t a2, uint32_t a3,
                                        uint32_t b0, uint32_t b1) {
    asm volatile(
        "mma.sync.aligned.m16n8k16.row.col.f32.f16.f16.f32 "
        "{%0,%1,%2,%3}, {%4,%5,%6,%7}, {%8,%9}, {%0,%1,%2,%3};"
        : "+f"(c[0]), "+f"(c[1]), "+f"(c[2]), "+f"(c[3])
        : "r"(a0), "r"(a1), "r"(a2), "r"(a3), "r"(b0), "r"(b1));
}

__device__ __forceinline__ void ldsm_x4(uint32_t r[4], uint32_t addr) {
    asm volatile("ldmatrix.sync.aligned.m8n8.x4.shared.b16 {%0,%1,%2,%3}, [%4];"
                 : "=r"(r[0]), "=r"(r[1]), "=r"(r[2]), "=r"(r[3]) : "r"(addr));
}
__device__ __forceinline__ void ldsm_x4_t(uint32_t r[4], uint32_t addr) {
    asm volatile("ldmatrix.sync.aligned.m8n8.x4.trans.shared.b16 {%0,%1,%2,%3}, [%4];"
                 : "=r"(r[0]), "=r"(r[1]), "=r"(r[2]), "=r"(r[3]) : "r"(addr));
}

__device__ __forceinline__ void cp_async16(uint32_t dst, const void* src) {
    asm volatile("cp.async.cg.shared.global [%0], [%1], 16;" :: "r"(dst), "l"(src));
}
__device__ __forceinline__ void cp_commit() {
    asm volatile("cp.async.commit_group;");
}
template <int N>
__device__ __forceinline__ void cp_wait() {
    asm volatile("cp.async.wait_group %0;" :: "n"(N));
}

// ---------------------------------------------------------------------------
// transpose + fp16-convert: src f32 [R][C] -> dst f16 [C][R]. R,C mult of 32.
// ---------------------------------------------------------------------------
__global__ __launch_bounds__(256) void transpose_h_kernel(
    const float* __restrict__ src, __half* __restrict__ dst, int R, int C)
{
    __shared__ float t[32][33];
    const int bx = blockIdx.x * 32;
    const int by = blockIdx.y * 32;
    const int tx = threadIdx.x;
    const int ty = threadIdx.y;

    #pragma unroll
    for (int i = 0; i < 4; i++)
        t[ty + i * 8][tx] = src[(size_t)(by + ty + i * 8) * C + bx + tx];
    __syncthreads();
    #pragma unroll
    for (int i = 0; i < 4; i++)
        dst[(size_t)(bx + ty + i * 8) * R + by + tx] = __float2half_rn(t[tx][ty + i * 8]);
}

// ---------------------------------------------------------------------------
// LayerNorm: one block per row, 256 threads; emits fp16 xn
// ---------------------------------------------------------------------------
__global__ __launch_bounds__(256) void ln_kernel(
    const float* __restrict__ x,
    const float* __restrict__ gamma,
    const float* __restrict__ beta,
    __half* __restrict__ xn)
{
    __shared__ float red[8];
    const int row = blockIdx.x;
    const int tid = threadIdx.x;
    const float* xr = x + (size_t)row * DIM;

    float4 v = *(const float4*)(xr + tid * 4);

    float s = v.x + v.y + v.z + v.w;
    #pragma unroll
    for (int o = 16; o > 0; o >>= 1) s += __shfl_xor_sync(0xffffffffu, s, o);
    if ((tid & 31) == 0) red[tid >> 5] = s;
    __syncthreads();
    if (tid < 8) {
        float t = red[tid];
        #pragma unroll
        for (int o = 4; o > 0; o >>= 1) t += __shfl_xor_sync(0xffu, t, o);
        if (tid == 0) red[0] = t;
    }
    __syncthreads();
    const float mu = red[0] * (1.0f / DIM);
    __syncthreads();

    float d0 = v.x - mu, d1 = v.y - mu, d2 = v.z - mu, d3 = v.w - mu;
    float sq = d0 * d0 + d1 * d1 + d2 * d2 + d3 * d3;
    #pragma unroll
    for (int o = 16; o > 0; o >>= 1) sq += __shfl_xor_sync(0xffffffffu, sq, o);
    if ((tid & 31) == 0) red[tid >> 5] = sq;
    __syncthreads();
    if (tid < 8) {
        float t = red[tid];
        #pragma unroll
        for (int o = 4; o > 0; o >>= 1) t += __shfl_xor_sync(0xffu, t, o);
        if (tid == 0) red[0] = t;
    }
    __syncthreads();
    const float inv = rsqrtf(red[0] * (1.0f / DIM) + LN_EPS);

    const int c = tid * 4;
    float4 g = *(const float4*)(gamma + c);
    float4 b = *(const float4*)(beta + c);
    uint2 o;
    o.x = pack_h2(d0 * inv * g.x + b.x, d1 * inv * g.y + b.y);
    o.y = pack_h2(d2 * inv * g.z + b.z, d3 * inv * g.w + b.w);
    *(uint2*)(xn + (size_t)row * DIM + c) = o;
}

// ---------------------------------------------------------------------------
// FP16 tensor-core GEMM (m16n8k16), ldmatrix fragments, cp.async TRIPLE
// buffer, BK=64 halves, ONE __syncthreads per slab (wait -> sync -> compute
// -> load(s+2) -> commit; the load targets buffer (s-1)%3 whose readers all
// finished before this iteration's barrier). C[M,N] = A[M,K] @ B^T;
// A f16 [M][K], B f16 transposed [N][K]. Block 256 thr (8 warps, 4m x 2n).
// ---------------------------------------------------------------------------
#define LDT2 72
#define STAGE_H (128 * LDT2)     // halves per tile per stage (18432 B)
__global__ __launch_bounds__(256) void f16_gemm(
    int M, int N, int K, int outHalf,
    const __half* __restrict__ A,
    const __half* __restrict__ B,
    void* __restrict__ Cv)
{
    __shared__ __half As[3][STAGE_H];
    __shared__ __half Bs[3][STAGE_H];

    const int tid  = threadIdx.x;
    const int warp = tid >> 5;
    const int lane = tid & 31;
    const int lr = lane >> 2;
    const int lc = lane & 3;

    const int wm = (warp & 3) * 32;
    const int wn = (warp >> 2) * 64;

    A += (size_t)blockIdx.y * 128 * K;
    B += (size_t)blockIdx.x * 128 * K;
    const size_t cOff = (size_t)blockIdx.y * 128 * N + blockIdx.x * 128;

    const int r0 = tid >> 3;             // 0..31
    const int kc = (tid & 7) * 8;        // half-col 0..56

    const uint32_t asBase = (uint32_t)__cvta_generic_to_shared(As);
    const uint32_t bsBase = (uint32_t)__cvta_generic_to_shared(Bs);

    const int nSlab = K / 64;

    auto load_slab = [&](int s, int buf) {
        const int gk = s * 64 + kc;
        const uint32_t ad = asBase + (uint32_t)(buf * STAGE_H * 2);
        const uint32_t bd = bsBase + (uint32_t)(buf * STAGE_H * 2);
        #pragma unroll
        for (int i = 0; i < 4; i++) {
            const int r = r0 + i * 32;
            cp_async16(ad + (uint32_t)((r * LDT2 + kc) * 2), A + (size_t)r * K + gk);
            cp_async16(bd + (uint32_t)((r * LDT2 + kc) * 2), B + (size_t)r * K + gk);
        }
    };

    const int aoff = (wm + (lane & 15)) * LDT2 + ((lane >> 4) << 3);
    const int boff = (wn + ((lane >> 4) << 3) + (lane & 7)) * LDT2 + (((lane >> 3) & 1) << 3);

    float acc[2][8][4] = {};

    load_slab(0, 0); cp_commit();
    load_slab(1, 1); cp_commit();

    for (int s = 0; s < nSlab; s++) {
        const int cur = s % 3;

        cp_wait<1>();            // slab s's group landed
        __syncthreads();         // the ONLY barrier per slab

        const uint32_t aStage = asBase + (uint32_t)(cur * STAGE_H * 2);
        const uint32_t bStage = bsBase + (uint32_t)(cur * STAGE_H * 2);

        #pragma unroll
        for (int ks = 0; ks < 64; ks += 16) {
            uint32_t afr[2][4];
            #pragma unroll
            for (int mi = 0; mi < 2; mi++)
                ldsm_x4(afr[mi], aStage + (uint32_t)((aoff + mi * 16 * LDT2 + ks) * 2));
            uint32_t bfr[4][4];
            #pragma unroll
            for (int j = 0; j < 4; j++)
                ldsm_x4(bfr[j], bStage + (uint32_t)((boff + j * 16 * LDT2 + ks) * 2));
            #pragma unroll
            for (int mi = 0; mi < 2; mi++)
                #pragma unroll
                for (int j = 0; j < 4; j++) {
                    mma_f16(acc[mi][2 * j],     afr[mi][0], afr[mi][1], afr[mi][2], afr[mi][3],
                            bfr[j][0], bfr[j][1]);
                    mma_f16(acc[mi][2 * j + 1], afr[mi][0], afr[mi][1], afr[mi][2], afr[mi][3],
                            bfr[j][2], bfr[j][3]);
                }
        }

        // load after compute (R6-proven ordering); one commit per iteration
        if (s + 2 < nSlab) load_slab(s + 2, (s + 2) % 3);
        cp_commit();
    }

    if (outHalf) {
        __half* C = (__half*)Cv + cOff;
        #pragma unroll
        for (int mi = 0; mi < 2; mi++) {
            const int r = wm + 16 * mi + lr;
            #pragma unroll
            for (int ni = 0; ni < 8; ni++) {
                const int c0 = wn + 8 * ni + 2 * lc;
                *(uint32_t*)(C + (size_t)r * N + c0)       = pack_h2(acc[mi][ni][0], acc[mi][ni][1]);
                *(uint32_t*)(C + (size_t)(r + 8) * N + c0) = pack_h2(acc[mi][ni][2], acc[mi][ni][3]);
            }
        }
    } else {
        float* C = (float*)Cv + cOff;
        #pragma unroll
        for (int mi = 0; mi < 2; mi++) {
            const int r = wm + 16 * mi + lr;
            #pragma unroll
            for (int ni = 0; ni < 8; ni++) {
                const int c0 = wn + 8 * ni + 2 * lc;
                *(float2*)(C + (size_t)r * N + c0)       = make_float2(acc[mi][ni][0], acc[mi][ni][1]);
                *(float2*)(C + (size_t)(r + 8) * N + c0) = make_float2(acc[mi][ni][2], acc[mi][ni][3]);
            }
        }
    }
}

// ---------------------------------------------------------------------------
// FlashAttention, FP16 mma (m16n8k16), exact (non-online) softmax, with
// cp.async TRIPLE-buffered K/V tiles and ONE barrier per tile (same proven
// structure as the GEMM). Block = 256 threads (8 warps), 128 query rows.
// ---------------------------------------------------------------------------
__global__ __launch_bounds__(256) void attn_mma_kernel(
    const __half* __restrict__ qkv,
    __half* __restrict__ attn_out)
{
    const int bh = blockIdx.y;
    const int b = bh / HEADS;
    const int h = bh % HEADS;
    const int qbase = blockIdx.x * 128;
    const int warp = threadIdx.x >> 5;
    const int lane = threadIdx.x & 31;
    const int lr = lane >> 2;
    const int lc = lane & 3;

    __shared__ __half Ks[3][64][LDT2];
    __shared__ __half Vs[3][64][LDT2];

    const __half* base = qkv + (size_t)b * NSEQ * QKV_W;
    const float NEG_INF = __int_as_float(0xff800000);
    const float QSCALE = SCALE * LOG2E;

    const int diagTile = blockIdx.x * 2 + ((warp & 4) >> 2);  // tile idx owning this warp's diagonal

    const uint32_t ksBase = (uint32_t)__cvta_generic_to_shared(Ks);
    const uint32_t vsBase = (uint32_t)__cvta_generic_to_shared(Vs);
    const uint32_t TILE_B = (uint32_t)(64 * LDT2 * 2);   // bytes per K (or V) stage

    // loader: 512 16B-chunks per matrix per tile; 256 thr x 2 per matrix
    auto load_tile = [&](int kt, int buf) {
        #pragma unroll
        for (int it = 0; it < 2; it++) {
            const int idx = threadIdx.x + it * 256;
            const int r  = idx >> 3;
            const int cc = (idx & 7) * 8;
            const __half* src = base + (size_t)(kt + r) * QKV_W + INNER + h * DHEAD + cc;
            const uint32_t off = (uint32_t)(buf) * TILE_B + (uint32_t)((r * LDT2 + cc) * 2);
            cp_async16(ksBase + off, src);
            cp_async16(vsBase + off, src + INNER);
        }
    };

    // K fragment offset (non-trans): rows = keys, col = d
    const int koff = (((lane >> 4) << 3) + (lane & 7)) * LDT2 + (((lane >> 3) & 1) << 3);
    // V fragment offset (trans): rows = keys, col = d
    const int voff = ((((lane >> 3) & 1) << 3) + (lane & 7)) * LDT2 + ((lane >> 4) << 3);

    // ---- Q fragments (fp16 pairs, pre-scaled by SCALE*log2e) ----
    uint32_t qa[4][4];
    {
        const int r0 = qbase + warp * 16 + lr;
        const __half* q0 = base + (size_t)r0 * QKV_W + h * DHEAD;
        const __half* q1 = q0 + (size_t)8 * QKV_W;
        #pragma unroll
        for (int s = 0; s < 4; s++) {
            const int d0 = 16 * s + 2 * lc;
            qa[s][0] = pack_h2(__half2float(q0[d0])     * QSCALE, __half2float(q0[d0 + 1]) * QSCALE);
            qa[s][1] = pack_h2(__half2float(q1[d0])     * QSCALE, __half2float(q1[d0 + 1]) * QSCALE);
            qa[s][2] = pack_h2(__half2float(q0[d0 + 8]) * QSCALE, __half2float(q0[d0 + 9]) * QSCALE);
            qa[s][3] = pack_h2(__half2float(q1[d0 + 8]) * QSCALE, __half2float(q1[d0 + 9]) * QSCALE);
        }
    }

    float oa[8][4] = {};
    float l0 = 0.0f, l1 = 0.0f;

    const int nTile = NSEQ / 64;
    load_tile(0, 0); cp_commit();
    load_tile(64, 1); cp_commit();

    for (int ti = 0; ti < nTile; ti++) {
        const int cur = ti % 3;

        cp_wait<1>();
        __syncthreads();         // the ONLY barrier per tile

        const uint32_t kStage = ksBase + (uint32_t)cur * TILE_B;
        const uint32_t vStage = vsBase + (uint32_t)cur * TILE_B;

        // ---- S' = (Q*scale*log2e) @ K^T : 4 ksteps (d) x 4 key-blocks ----
        float sfr[8][4] = {};
        #pragma unroll
        for (int s = 0; s < 4; s++) {
            #pragma unroll
            for (int j = 0; j < 4; j++) {
                uint32_t kb[4];
                ldsm_x4(kb, kStage + (uint32_t)((16 * j * LDT2 + koff + 16 * s) * 2));
                mma_f16(sfr[2 * j],     qa[s][0], qa[s][1], qa[s][2], qa[s][3], kb[0], kb[1]);
                mma_f16(sfr[2 * j + 1], qa[s][0], qa[s][1], qa[s][2], qa[s][3], kb[2], kb[3]);
            }
        }

        // ---- diagonal mask (warp-local diagonal tile) ----
        if (ti == diagTile) {
            const int rloc0 = 16 * (warp & 3) + lr;
            const int rloc1 = rloc0 + 8;
            #pragma unroll
            for (int n = 0; n < 8; n++) {
                const int col0 = 8 * n + 2 * lc;
                if (col0 == rloc0)     sfr[n][0] = NEG_INF;
                if (col0 + 1 == rloc0) sfr[n][1] = NEG_INF;
                if (col0 == rloc1)     sfr[n][2] = NEG_INF;
                if (col0 + 1 == rloc1) sfr[n][3] = NEG_INF;
            }
        }

        // ---- P = f16(exp2(S')); pack A-fragments; l from rounded values ----
        uint32_t pa[4][4];
        #pragma unroll
        for (int s = 0; s < 4; s++) {
            pa[s][0] = pack_h2(exp2_fast(sfr[2 * s][0]),     exp2_fast(sfr[2 * s][1]));
            pa[s][1] = pack_h2(exp2_fast(sfr[2 * s][2]),     exp2_fast(sfr[2 * s][3]));
            pa[s][2] = pack_h2(exp2_fast(sfr[2 * s + 1][0]), exp2_fast(sfr[2 * s + 1][1]));
            pa[s][3] = pack_h2(exp2_fast(sfr[2 * s + 1][2]), exp2_fast(sfr[2 * s + 1][3]));
            float2 f0 = unpack_h2(pa[s][0]);
            float2 f1 = unpack_h2(pa[s][1]);
            float2 f2 = unpack_h2(pa[s][2]);
            float2 f3 = unpack_h2(pa[s][3]);
            l0 += f0.x + f0.y + f2.x + f2.y;
            l1 += f1.x + f1.y + f3.x + f3.y;
        }

        // ---- O += P @ V : 4 ksteps (keys) x 4 d-blocks; V via trans ----
        #pragma unroll
        for (int s = 0; s < 4; s++) {
            #pragma unroll
            for (int j = 0; j < 4; j++) {
                uint32_t vb[4];
                ldsm_x4_t(vb, vStage + (uint32_t)((16 * s * LDT2 + voff + 16 * j) * 2));
                mma_f16(oa[2 * j],     pa[s][0], pa[s][1], pa[s][2], pa[s][3], vb[0], vb[1]);
                mma_f16(oa[2 * j + 1], pa[s][0], pa[s][1], pa[s][2], pa[s][3], vb[2], vb[3]);
            }
        }

        // load after compute; one commit per iteration
        if (ti + 2 < nTile) load_tile((ti + 2) * 64, (ti + 2) % 3);
        cp_commit();
    }

    l0 += __shfl_xor_sync(0xffffffffu, l0, 1);
    l0 += __shfl_xor_sync(0xffffffffu, l0, 2);
    l1 += __shfl_xor_sync(0xffffffffu, l1, 1);
    l1 += __shfl_xor_sync(0xffffffffu, l1, 2);
    const float inv0 = 1.0f / l0;
    const float inv1 = 1.0f / l1;

    const int row0 = qbase + 16 * warp + lr;
    __half* o0 = attn_out + ((size_t)b * NSEQ + row0) * INNER + h * DHEAD;
    __half* o1 = o0 + (size_t)8 * INNER;
    #pragma unroll
    for (int n = 0; n < 8; n++) {
        const int c = 8 * n + 2 * lc;
        *(uint32_t*)(o0 + c) = pack_h2(oa[n][0] * inv0, oa[n][1] * inv0);
        *(uint32_t*)(o1 + c) = pack_h2(oa[n][2] * inv1, oa[n][3] * inv1);
    }
}

// ---------------------------------------------------------------------------
extern "C" void kernel_launch(void* const* d_in, const int* in_sizes, int n_in,
                              void* d_out, int out_size)
{
    const float* x      = (const float*)d_in[0];
    const float* gamma  = (const float*)d_in[1];
    const float* beta   = (const float*)d_in[2];
    const float* w_qkv  = (const float*)d_in[3];
    const float* w_out  = (const float*)d_in[4];
    float* out = (float*)d_out;

    __half *xn, *qkv, *attn, *wqkvT, *woutT;
    cudaGetSymbolAddress((void**)&xn,    g_xn);
    cudaGetSymbolAddress((void**)&qkv,   g_qkv);
    cudaGetSymbolAddress((void**)&attn,  g_attn);
    cudaGetSymbolAddress((void**)&wqkvT, g_wqkvT);
    cudaGetSymbolAddress((void**)&woutT, g_woutT);

    // 0) transpose + convert weights: f32 [K][N] -> f16 [N][K]
    {
        dim3 blk(32, 8);
        dim3 g1(QKV_W / 32, DIM / 32);
        transpose_h_kernel<<<g1, blk>>>(w_qkv, wqkvT, DIM, QKV_W);
        dim3 g2(DIM / 32, INNER / 32);
        transpose_h_kernel<<<g2, blk>>>(w_out, woutT, INNER, DIM);
    }

    // 1) LayerNorm (emits fp16)
    ln_kernel<<<ROWS, 256>>>(x, gamma, beta, xn);

    // 2) QKV projection: [4096,1024] @ [1024,3072], fp16 output
    {
        dim3 grid(QKV_W / 128, ROWS / 128);
        f16_gemm<<<grid, 256>>>(ROWS, QKV_W, DIM, 1, xn, wqkvT, qkv);
    }

    // 3) attention (128 q-rows per block, fp16 mma)
    {
        dim3 grid(NSEQ / 128, BATCH * HEADS);
        attn_mma_kernel<<<grid, 256>>>(qkv, attn);
    }

    // 4) output projection: [4096,1024] @ [1024,1024], fp32 output
    {
        dim3 grid(DIM / 128, ROWS / 128);
        f16_gemm<<<grid, 256>>>(ROWS, DIM, INNER, 0, attn, woutT, out);
    }
}

// round 13
// speedup vs baseline: 2.0995x; 1.0544x over previous
#include <cuda_runtime.h>
#include <cuda_fp16.h>
#include <math.h>
#include <stdint.h>

// Problem constants
#define BATCH 2
#define NSEQ 2048
#define DIM 1024
#define HEADS 16
#define DHEAD 64
#define INNER (HEADS * DHEAD)      // 1024
#define QKV_W (3 * INNER)          // 3072
#define ROWS (BATCH * NSEQ)        // 4096
#define SCALE 0.125f               // 64^-0.5
#define LN_EPS 1e-5f
#define LOG2E 1.4426950408889634f

// Scratch (device globals: allocation-free rule) — all fp16
__device__ __half g_xn[ROWS * DIM];        //  8 MB
__device__ __half g_qkv[ROWS * QKV_W];     // 24 MB
__device__ __half g_attn[ROWS * INNER];    //  8 MB
__device__ __half g_wqkvT[QKV_W * DIM];    //  6 MB (transposed [N][K])
__device__ __half g_woutT[DIM * INNER];    //  2 MB (transposed [N][K])

// ---------------------------------------------------------------------------
// helpers
// ---------------------------------------------------------------------------
__device__ __forceinline__ float exp2_fast(float x) {
    float y;
    asm("ex2.approx.ftz.f32 %0, %1;" : "=f"(y) : "f"(x));
    return y;
}
__device__ __forceinline__ uint32_t pack_h2(float lo, float hi) {
    uint32_t d;
    asm("cvt.rn.f16x2.f32 %0, %1, %2;" : "=r"(d) : "f"(hi), "f"(lo));
    return d;
}
__device__ __forceinline__ float2 unpack_h2(uint32_t u) {
    __half2 h = *reinterpret_cast<__half2*>(&u);
    return __half22float2(h);
}

__device__ __forceinline__ void mma_f16(float c[4],
                                        uint32_t a0, uint32_t a1, uint32_t a2, uint32_t a3,
                                        uint32_t b0, uint32_t b1) {
    asm volatile(
        "mma.sync.aligned.m16n8k16.row.col.f32.f16.f16.f32 "
        "{%0,%1,%2,%3}, {%4,%5,%6,%7}, {%8,%9}, {%0,%1,%2,%3};"
        : "+f"(c[0]), "+f"(c[1]), "+f"(c[2]), "+f"(c[3])
        : "r"(a0), "r"(a1), "r"(a2), "r"(a3), "r"(b0), "r"(b1));
}

__device__ __forceinline__ void ldsm_x4(uint32_t r[4], uint32_t addr) {
    asm volatile("ldmatrix.sync.aligned.m8n8.x4.shared.b16 {%0,%1,%2,%3}, [%4];"
                 : "=r"(r[0]), "=r"(r[1]), "=r"(r[2]), "=r"(r[3]) : "r"(addr));
}
__device__ __forceinline__ void ldsm_x4_t(uint32_t r[4], uint32_t addr) {
    asm volatile("ldmatrix.sync.aligned.m8n8.x4.trans.shared.b16 {%0,%1,%2,%3}, [%4];"
                 : "=r"(r[0]), "=r"(r[1]), "=r"(r[2]), "=r"(r[3]) : "r"(addr));
}

__device__ __forceinline__ void cp_async16(uint32_t dst, const void* src) {
    asm volatile("cp.async.cg.shared.global [%0], [%1], 16;" :: "r"(dst), "l"(src));
}
__device__ __forceinline__ void cp_commit() {
    asm volatile("cp.async.commit_group;");
}
template <int N>
__device__ __forceinline__ void cp_wait() {
    asm volatile("cp.async.wait_group %0;" :: "n"(N));
}

// ---------------------------------------------------------------------------
// fused preprocessing: both weight transposes + LayerNorm in ONE launch.
// blocks [0, NT1): transpose w_qkv; [NT1, NT1+NT2): transpose w_out;
// [NT1+NT2, +ROWS): LayerNorm rows. 256 threads each.
// ---------------------------------------------------------------------------
#define NT1 ((QKV_W / 32) * (DIM / 32))     // 3072
#define NT2 ((DIM / 32) * (INNER / 32))     // 1024

__device__ void transpose_tile(const float* __restrict__ src, __half* __restrict__ dst,
                               int R, int C, int bx, int by)
{
    __shared__ float t[32][33];
    const int tx = threadIdx.x & 31;
    const int ty = threadIdx.x >> 5;   // 0..7

    #pragma unroll
    for (int i = 0; i < 4; i++)
        t[ty + i * 8][tx] = src[(size_t)(by + ty + i * 8) * C + bx + tx];
    __syncthreads();
    #pragma unroll
    for (int i = 0; i < 4; i++)
        dst[(size_t)(bx + ty + i * 8) * R + by + tx] = __float2half_rn(t[tx][ty + i * 8]);
}

__device__ void ln_row(const float* __restrict__ x,
                       const float* __restrict__ gamma,
                       const float* __restrict__ beta,
                       __half* __restrict__ xn, int row)
{
    __shared__ float red[8];
    const int tid = threadIdx.x;
    const float* xr = x + (size_t)row * DIM;

    float4 v = *(const float4*)(xr + tid * 4);

    float s = v.x + v.y + v.z + v.w;
    #pragma unroll
    for (int o = 16; o > 0; o >>= 1) s += __shfl_xor_sync(0xffffffffu, s, o);
    if ((tid & 31) == 0) red[tid >> 5] = s;
    __syncthreads();
    if (tid < 8) {
        float t = red[tid];
        #pragma unroll
        for (int o = 4; o > 0; o >>= 1) t += __shfl_xor_sync(0xffu, t, o);
        if (tid == 0) red[0] = t;
    }
    __syncthreads();
    const float mu = red[0] * (1.0f / DIM);
    __syncthreads();

    float d0 = v.x - mu, d1 = v.y - mu, d2 = v.z - mu, d3 = v.w - mu;
    float sq = d0 * d0 + d1 * d1 + d2 * d2 + d3 * d3;
    #pragma unroll
    for (int o = 16; o > 0; o >>= 1) sq += __shfl_xor_sync(0xffffffffu, sq, o);
    if ((tid & 31) == 0) red[tid >> 5] = sq;
    __syncthreads();
    if (tid < 8) {
        float t = red[tid];
        #pragma unroll
        for (int o = 4; o > 0; o >>= 1) t += __shfl_xor_sync(0xffu, t, o);
        if (tid == 0) red[0] = t;
    }
    __syncthreads();
    const float inv = rsqrtf(red[0] * (1.0f / DIM) + LN_EPS);

    const int c = tid * 4;
    float4 g = *(const float4*)(gamma + c);
    float4 b = *(const float4*)(beta + c);
    uint2 o;
    o.x = pack_h2(d0 * inv * g.x + b.x, d1 * inv * g.y + b.y);
    o.y = pack_h2(d2 * inv * g.z + b.z, d3 * inv * g.w + b.w);
    *(uint2*)(xn + (size_t)row * DIM + c) = o;
}

__global__ __launch_bounds__(256) void prep_kernel(
    const float* __restrict__ x,
    const float* __restrict__ gamma,
    const float* __restrict__ beta,
    const float* __restrict__ w_qkv,
    const float* __restrict__ w_out,
    __half* __restrict__ xn,
    __half* __restrict__ wqkvT,
    __half* __restrict__ woutT)
{
    const int bid = blockIdx.x;
    if (bid < NT1) {
        const int bx = (bid % (QKV_W / 32)) * 32;
        const int by = (bid / (QKV_W / 32)) * 32;
        transpose_tile(w_qkv, wqkvT, DIM, QKV_W, bx, by);
    } else if (bid < NT1 + NT2) {
        const int id = bid - NT1;
        const int bx = (id % (DIM / 32)) * 32;
        const int by = (id / (DIM / 32)) * 32;
        transpose_tile(w_out, woutT, INNER, DIM, bx, by);
    } else {
        ln_row(x, gamma, beta, xn, bid - NT1 - NT2);
    }
}

// ---------------------------------------------------------------------------
// FP16 tensor-core GEMM (m16n8k16), ldmatrix fragments, cp.async TRIPLE
// buffer, BK=64 halves, ONE __syncthreads per slab. (R12, unchanged.)
// ---------------------------------------------------------------------------
#define LDT2 72
#define STAGE_H (128 * LDT2)
__global__ __launch_bounds__(256) void f16_gemm(
    int M, int N, int K, int outHalf,
    const __half* __restrict__ A,
    const __half* __restrict__ B,
    void* __restrict__ Cv)
{
    __shared__ __half As[3][STAGE_H];
    __shared__ __half Bs[3][STAGE_H];

    const int tid  = threadIdx.x;
    const int warp = tid >> 5;
    const int lane = tid & 31;
    const int lr = lane >> 2;
    const int lc = lane & 3;

    const int wm = (warp & 3) * 32;
    const int wn = (warp >> 2) * 64;

    A += (size_t)blockIdx.y * 128 * K;
    B += (size_t)blockIdx.x * 128 * K;
    const size_t cOff = (size_t)blockIdx.y * 128 * N + blockIdx.x * 128;

    const int r0 = tid >> 3;
    const int kc = (tid & 7) * 8;

    const uint32_t asBase = (uint32_t)__cvta_generic_to_shared(As);
    const uint32_t bsBase = (uint32_t)__cvta_generic_to_shared(Bs);

    const int nSlab = K / 64;

    auto load_slab = [&](int s, int buf) {
        const int gk = s * 64 + kc;
        const uint32_t ad = asBase + (uint32_t)(buf * STAGE_H * 2);
        const uint32_t bd = bsBase + (uint32_t)(buf * STAGE_H * 2);
        #pragma unroll
        for (int i = 0; i < 4; i++) {
            const int r = r0 + i * 32;
            cp_async16(ad + (uint32_t)((r * LDT2 + kc) * 2), A + (size_t)r * K + gk);
            cp_async16(bd + (uint32_t)((r * LDT2 + kc) * 2), B + (size_t)r * K + gk);
        }
    };

    const int aoff = (wm + (lane & 15)) * LDT2 + ((lane >> 4) << 3);
    const int boff = (wn + ((lane >> 4) << 3) + (lane & 7)) * LDT2 + (((lane >> 3) & 1) << 3);

    float acc[2][8][4] = {};

    load_slab(0, 0); cp_commit();
    load_slab(1, 1); cp_commit();

    for (int s = 0; s < nSlab; s++) {
        const int cur = s % 3;

        cp_wait<1>();
        __syncthreads();

        const uint32_t aStage = asBase + (uint32_t)(cur * STAGE_H * 2);
        const uint32_t bStage = bsBase + (uint32_t)(cur * STAGE_H * 2);

        #pragma unroll
        for (int ks = 0; ks < 64; ks += 16) {
            uint32_t afr[2][4];
            #pragma unroll
            for (int mi = 0; mi < 2; mi++)
                ldsm_x4(afr[mi], aStage + (uint32_t)((aoff + mi * 16 * LDT2 + ks) * 2));
            uint32_t bfr[4][4];
            #pragma unroll
            for (int j = 0; j < 4; j++)
                ldsm_x4(bfr[j], bStage + (uint32_t)((boff + j * 16 * LDT2 + ks) * 2));
            #pragma unroll
            for (int mi = 0; mi < 2; mi++)
                #pragma unroll
                for (int j = 0; j < 4; j++) {
                    mma_f16(acc[mi][2 * j],     afr[mi][0], afr[mi][1], afr[mi][2], afr[mi][3],
                            bfr[j][0], bfr[j][1]);
                    mma_f16(acc[mi][2 * j + 1], afr[mi][0], afr[mi][1], afr[mi][2], afr[mi][3],
                            bfr[j][2], bfr[j][3]);
                }
        }

        if (s + 2 < nSlab) load_slab(s + 2, (s + 2) % 3);
        cp_commit();
    }

    if (outHalf) {
        __half* C = (__half*)Cv + cOff;
        #pragma unroll
        for (int mi = 0; mi < 2; mi++) {
            const int r = wm + 16 * mi + lr;
            #pragma unroll
            for (int ni = 0; ni < 8; ni++) {
                const int c0 = wn + 8 * ni + 2 * lc;
                *(uint32_t*)(C + (size_t)r * N + c0)       = pack_h2(acc[mi][ni][0], acc[mi][ni][1]);
                *(uint32_t*)(C + (size_t)(r + 8) * N + c0) = pack_h2(acc[mi][ni][2], acc[mi][ni][3]);
            }
        }
    } else {
        float* C = (float*)Cv + cOff;
        #pragma unroll
        for (int mi = 0; mi < 2; mi++) {
            const int r = wm + 16 * mi + lr;
            #pragma unroll
            for (int ni = 0; ni < 8; ni++) {
                const int c0 = wn + 8 * ni + 2 * lc;
                *(float2*)(C + (size_t)r * N + c0)       = make_float2(acc[mi][ni][0], acc[mi][ni][1]);
                *(float2*)(C + (size_t)(r + 8) * N + c0) = make_float2(acc[mi][ni][2], acc[mi][ni][3]);
            }
        }
    }
}

// ---------------------------------------------------------------------------
// FlashAttention, FP16 mma, exact softmax, cp.async triple buffer.
// NEW: 4 warps (128 thr), each warp owns m32 (two m16 tiles) -> every
// ldmatrix K/V fragment feeds 4 mma instead of 2, halving smem-read traffic
// (the measured co-binding constraint). 128 q-rows per block for one (b,h).
// ---------------------------------------------------------------------------
__global__ __launch_bounds__(128) void attn_mma_kernel(
    const __half* __restrict__ qkv,
    __half* __restrict__ attn_out)
{
    const int bh = blockIdx.y;
    const int b = bh / HEADS;
    const int h = bh % HEADS;
    const int qbase = blockIdx.x * 128;
    const int warp = threadIdx.x >> 5;   // 0..3
    const int lane = threadIdx.x & 31;
    const int lr = lane >> 2;
    const int lc = lane & 3;

    __shared__ __half Ks[3][64][LDT2];
    __shared__ __half Vs[3][64][LDT2];

    const __half* base = qkv + (size_t)b * NSEQ * QKV_W;
    const float NEG_INF = __int_as_float(0xff800000);
    const float QSCALE = SCALE * LOG2E;

    // warp rows qbase+32w .. +31 lie inside 64-key tile (blockIdx.x*2 + (w>>1))
    const int diagTile = blockIdx.x * 2 + (warp >> 1);

    const uint32_t ksBase = (uint32_t)__cvta_generic_to_shared(Ks);
    const uint32_t vsBase = (uint32_t)__cvta_generic_to_shared(Vs);
    const uint32_t TILE_B = (uint32_t)(64 * LDT2 * 2);

    // loader: 512 16B-chunks per matrix per tile; 128 thr x 4 per matrix
    auto load_tile = [&](int kt, int buf) {
        #pragma unroll
        for (int it = 0; it < 4; it++) {
            const int idx = threadIdx.x + it * 128;   // 0..511
            const int r  = idx >> 3;
            const int cc = (idx & 7) * 8;
            const __half* src = base + (size_t)(kt + r) * QKV_W + INNER + h * DHEAD + cc;
            const uint32_t off = (uint32_t)(buf) * TILE_B + (uint32_t)((r * LDT2 + cc) * 2);
            cp_async16(ksBase + off, src);
            cp_async16(vsBase + off, src + INNER);
        }
    };

    const int koff = (((lane >> 4) << 3) + (lane & 7)) * LDT2 + (((lane >> 3) & 1) << 3);
    const int voff = ((((lane >> 3) & 1) << 3) + (lane & 7)) * LDT2 + ((lane >> 4) << 3);

    // ---- Q fragments for both m16 tiles (mi = 0, 1) ----
    uint32_t qa[2][4][4];
    #pragma unroll
    for (int mi = 0; mi < 2; mi++) {
        const int r0 = qbase + 32 * warp + 16 * mi + lr;
        const __half* q0 = base + (size_t)r0 * QKV_W + h * DHEAD;
        const __half* q1 = q0 + (size_t)8 * QKV_W;
        #pragma unroll
        for (int s = 0; s < 4; s++) {
            const int d0 = 16 * s + 2 * lc;
            qa[mi][s][0] = pack_h2(__half2float(q0[d0])     * QSCALE, __half2float(q0[d0 + 1]) * QSCALE);
            qa[mi][s][1] = pack_h2(__half2float(q1[d0])     * QSCALE, __half2float(q1[d0 + 1]) * QSCALE);
            qa[mi][s][2] = pack_h2(__half2float(q0[d0 + 8]) * QSCALE, __half2float(q0[d0 + 9]) * QSCALE);
            qa[mi][s][3] = pack_h2(__half2float(q1[d0 + 8]) * QSCALE, __half2float(q1[d0 + 9]) * QSCALE);
        }
    }

    float oa[2][8][4] = {};
    float l0[2] = {0.0f, 0.0f}, l1[2] = {0.0f, 0.0f};

    const int nTile = NSEQ / 64;
    load_tile(0, 0); cp_commit();
    load_tile(64, 1); cp_commit();

    for (int ti = 0; ti < nTile; ti++) {
        const int cur = ti % 3;

        cp_wait<1>();
        __syncthreads();

        const uint32_t kStage = ksBase + (uint32_t)cur * TILE_B;
        const uint32_t vStage = vsBase + (uint32_t)cur * TILE_B;

        // ---- S' = Qs @ K^T : each kb feeds 4 mma (2 mi x 2 n-halves) ----
        float sfr[2][8][4] = {};
        #pragma unroll
        for (int s = 0; s < 4; s++) {
            #pragma unroll
            for (int j = 0; j < 4; j++) {
                uint32_t kb[4];
                ldsm_x4(kb, kStage + (uint32_t)((16 * j * LDT2 + koff + 16 * s) * 2));
                #pragma unroll
                for (int mi = 0; mi < 2; mi++) {
                    mma_f16(sfr[mi][2 * j],     qa[mi][s][0], qa[mi][s][1], qa[mi][s][2], qa[mi][s][3],
                            kb[0], kb[1]);
                    mma_f16(sfr[mi][2 * j + 1], qa[mi][s][0], qa[mi][s][1], qa[mi][s][2], qa[mi][s][3],
                            kb[2], kb[3]);
                }
            }
        }

        // ---- diagonal mask ----
        if (ti == diagTile) {
            #pragma unroll
            for (int mi = 0; mi < 2; mi++) {
                const int rloc0 = ((warp & 1) << 5) + (mi << 4) + lr;
                const int rloc1 = rloc0 + 8;
                #pragma unroll
                for (int n = 0; n < 8; n++) {
                    const int col0 = 8 * n + 2 * lc;
                    if (col0 == rloc0)     sfr[mi][n][0] = NEG_INF;
                    if (col0 + 1 == rloc0) sfr[mi][n][1] = NEG_INF;
                    if (col0 == rloc1)     sfr[mi][n][2] = NEG_INF;
                    if (col0 + 1 == rloc1) sfr[mi][n][3] = NEG_INF;
                }
            }
        }

        // ---- P = f16(exp2(S')); pack A-fragments; l from rounded values ----
        uint32_t pa[2][4][4];
        #pragma unroll
        for (int mi = 0; mi < 2; mi++) {
            #pragma unroll
            for (int s = 0; s < 4; s++) {
                pa[mi][s][0] = pack_h2(exp2_fast(sfr[mi][2 * s][0]),     exp2_fast(sfr[mi][2 * s][1]));
                pa[mi][s][1] = pack_h2(exp2_fast(sfr[mi][2 * s][2]),     exp2_fast(sfr[mi][2 * s][3]));
                pa[mi][s][2] = pack_h2(exp2_fast(sfr[mi][2 * s + 1][0]), exp2_fast(sfr[mi][2 * s + 1][1]));
                pa[mi][s][3] = pack_h2(exp2_fast(sfr[mi][2 * s + 1][2]), exp2_fast(sfr[mi][2 * s + 1][3]));
                float2 f0 = unpack_h2(pa[mi][s][0]);
                float2 f1 = unpack_h2(pa[mi][s][1]);
                float2 f2 = unpack_h2(pa[mi][s][2]);
                float2 f3 = unpack_h2(pa[mi][s][3]);
                l0[mi] += f0.x + f0.y + f2.x + f2.y;
                l1[mi] += f1.x + f1.y + f3.x + f3.y;
            }
        }

        // ---- O += P @ V : each vb feeds 4 mma (2 mi x 2 d-halves) ----
        #pragma unroll
        for (int s = 0; s < 4; s++) {
            #pragma unroll
            for (int j = 0; j < 4; j++) {
                uint32_t vb[4];
                ldsm_x4_t(vb, vStage + (uint32_t)((16 * s * LDT2 + voff + 16 * j) * 2));
                #pragma unroll
                for (int mi = 0; mi < 2; mi++) {
                    mma_f16(oa[mi][2 * j],     pa[mi][s][0], pa[mi][s][1], pa[mi][s][2], pa[mi][s][3],
                            vb[0], vb[1]);
                    mma_f16(oa[mi][2 * j + 1], pa[mi][s][0], pa[mi][s][1], pa[mi][s][2], pa[mi][s][3],
                            vb[2], vb[3]);
                }
            }
        }

        if (ti + 2 < nTile) load_tile((ti + 2) * 64, (ti + 2) % 3);
        cp_commit();
    }

    #pragma unroll
    for (int mi = 0; mi < 2; mi++) {
        l0[mi] += __shfl_xor_sync(0xffffffffu, l0[mi], 1);
        l0[mi] += __shfl_xor_sync(0xffffffffu, l0[mi], 2);
        l1[mi] += __shfl_xor_sync(0xffffffffu, l1[mi], 1);
        l1[mi] += __shfl_xor_sync(0xffffffffu, l1[mi], 2);
        const float inv0 = 1.0f / l0[mi];
        const float inv1 = 1.0f / l1[mi];

        const int row0 = qbase + 32 * warp + 16 * mi + lr;
        __half* o0 = attn_out + ((size_t)b * NSEQ + row0) * INNER + h * DHEAD;
        __half* o1 = o0 + (size_t)8 * INNER;
        #pragma unroll
        for (int n = 0; n < 8; n++) {
            const int c = 8 * n + 2 * lc;
            *(uint32_t*)(o0 + c) = pack_h2(oa[mi][n][0] * inv0, oa[mi][n][1] * inv0);
            *(uint32_t*)(o1 + c) = pack_h2(oa[mi][n][2] * inv1, oa[mi][n][3] * inv1);
        }
    }
}

// ---------------------------------------------------------------------------
extern "C" void kernel_launch(void* const* d_in, const int* in_sizes, int n_in,
                              void* d_out, int out_size)
{
    const float* x      = (const float*)d_in[0];
    const float* gamma  = (const float*)d_in[1];
    const float* beta   = (const float*)d_in[2];
    const float* w_qkv  = (const float*)d_in[3];
    const float* w_out  = (const float*)d_in[4];
    float* out = (float*)d_out;

    __half *xn, *qkv, *attn, *wqkvT, *woutT;
    cudaGetSymbolAddress((void**)&xn,    g_xn);
    cudaGetSymbolAddress((void**)&qkv,   g_qkv);
    cudaGetSymbolAddress((void**)&attn,  g_attn);
    cudaGetSymbolAddress((void**)&wqkvT, g_wqkvT);
    cudaGetSymbolAddress((void**)&woutT, g_woutT);

    // 0+1) fused: weight transposes + LayerNorm (one launch)
    prep_kernel<<<NT1 + NT2 + ROWS, 256>>>(x, gamma, beta, w_qkv, w_out,
                                           xn, wqkvT, woutT);

    // 2) QKV projection: [4096,1024] @ [1024,3072], fp16 output
    {
        dim3 grid(QKV_W / 128, ROWS / 128);
        f16_gemm<<<grid, 256>>>(ROWS, QKV_W, DIM, 1, xn, wqkvT, qkv);
    }

    // 3) attention (128 q-rows per block, 4 warps x m32)
    {
        dim3 grid(NSEQ / 128, BATCH * HEADS);
        attn_mma_kernel<<<grid, 128>>>(qkv, attn);
    }

    // 4) output projection: [4096,1024] @ [1024,1024], fp32 output
    {
        dim3 grid(DIM / 128, ROWS / 128);
        f16_gemm<<<grid, 256>>>(ROWS, DIM, INNER, 0, attn, woutT, out);
    }
}